// round 7
// baseline (speedup 1.0000x reference)
#include <cuda_runtime.h>
#include <utility>
#include <cstdint>

// ---------------------------------------------------------------------------
// Problem constants (fixed: LS=[0,1,2], OFF=[0,1,4], 11 paths, MUL=32, dim=9)
// ---------------------------------------------------------------------------
#define BASE_DIM 9
#define MUL 32
#define NPATHS 11
#define MAX_NODES 10000
#define ROW (MUL * BASE_DIM) /* 288 */
#define ROW4 (ROW / 4)       /* 72 */
#define MAXDEG 64
#define OVF_CAP 4096

struct BEntry { int i, j, k, p; };
struct BTable { BEntry e[96]; int n; };

// Compile-time enumeration of structural nonzeros of the real-basis Wigner-3j
// blocks (exact real-SH selection rules). Verified: rel_err ~8e-8.
constexpr BTable build_table() {
    constexpr int ls[3]  = {0, 1, 2};
    constexpr int off[3] = {0, 1, 4};
    constexpr int paths[NPATHS][3] = {
        {0,0,0},{1,1,0},{2,2,0},
        {0,1,1},{1,0,1},{1,2,1},{2,1,1},
        {0,2,2},{1,1,2},{2,0,2},{2,2,2}};
    BTable t{};
    t.n = 0;
    for (int p = 0; p < NPATHS; ++p) {
        const int la = ls[paths[p][0]], lb = ls[paths[p][1]], lc = ls[paths[p][2]];
        for (int m1 = -la; m1 <= la; ++m1)
        for (int m2 = -lb; m2 <= lb; ++m2)
        for (int m3 = -lc; m3 <= lc; ++m3) {
            const int a = m1 < 0 ? -m1 : m1;
            const int b = m2 < 0 ? -m2 : m2;
            const int c = m3 < 0 ? -m3 : m3;
            const int d = a > b ? a - b : b - a;
            if (c != a + b && c != d) continue;
            const int negs = (m1 < 0) + (m2 < 0) + (m3 < 0);
            if (negs & 1) continue;
            t.e[t.n].i = off[paths[p][0]] + la + m1;
            t.e[t.n].j = off[paths[p][1]] + lb + m2;
            t.e[t.n].k = off[paths[p][2]] + lc + m3;
            t.e[t.n].p = p;
            ++t.n;
        }
    }
    return t;
}

constexpr BTable TAB = build_table();
constexpr int NS = TAB.n;
static_assert(NS == 83, "expected 83 structural nonzeros");

struct PStarts { int v[NPATHS + 1]; };
constexpr PStarts build_pstarts() {
    PStarts r{};
    for (int p = 0; p <= NPATHS; ++p) {
        int c = 0;
        for (int s = 0; s < NS; ++s) if (TAB.e[s].p < p) ++c;
        r.v[p] = c;
    }
    return r;
}
constexpr PStarts PSTART = build_pstarts();

constexpr int PATH_K_BASE[NPATHS] = {0,0,0, 1,1,1,1, 4,4,4,4};
constexpr int PATH_K_CNT [NPATHS] = {1,1,1, 3,3,3,3, 5,5,5,5};

__constant__ BTable c_TAB = TAB;
__constant__ float c_VAL[96];

// ---------------------------------------------------------------------------
// Device scratch (no allocations allowed)
// ---------------------------------------------------------------------------
__device__ __align__(16) float g_scatter[(size_t)MAX_NODES * ROW]; // 11.52 MB
__device__ float g_cval[96];
__device__ int g_count[MAX_NODES];
__device__ int g_slots[(size_t)MAX_NODES * MAXDEG]; // 2.56 MB
__device__ int g_ovf_cnt;
__device__ int g_ovf[OVF_CAP];

// ---------------------------------------------------------------------------
// K0: zero per-node counters + overflow count
// ---------------------------------------------------------------------------
__global__ void zero_counters_kernel() {
    const int t = blockIdx.x * blockDim.x + threadIdx.x;
    if (t < MAX_NODES) g_count[t] = 0;
    if (t == 0) g_ovf_cnt = 0;
}

// ---------------------------------------------------------------------------
// K1: bucket-fill edge lists per node; block 0 extracts w3j entry values
// ---------------------------------------------------------------------------
__global__ void fill_kernel(const int* __restrict__ idxs, int E,
                            const float* __restrict__ w3j) {
    const int t = blockIdx.x * blockDim.x + threadIdx.x;
    if (blockIdx.x == 0 && threadIdx.x < 96) {
        const int s = threadIdx.x;
        if (s < NS) {
            const BEntry en = c_TAB.e[s];
            g_cval[s] = w3j[en.p * 729 + en.i * 81 + en.j * 9 + en.k];
        } else {
            g_cval[s] = 0.f;
        }
    }
    if (t >= E) return;
    const int node = idxs[t];
    const int slot = atomicAdd(&g_count[node], 1);
    if (slot < MAXDEG) {
        g_slots[node * MAXDEG + slot] = t;
    } else {
        const int o = atomicAdd(&g_ovf_cnt, 1);
        if (o < OVF_CAP) g_ovf[o] = t;
    }
}

// ---------------------------------------------------------------------------
// K2: warp-per-node accumulate: sum listed x2 rows (plain coalesced loads),
// single clean row write. Empty nodes get zero rows (replaces zero kernel).
// ---------------------------------------------------------------------------
__global__ __launch_bounds__(256)
void accumulate_kernel(const float* __restrict__ x2) {
    const int lane = threadIdx.x & 31;
    const int n = (blockIdx.x * blockDim.x + threadIdx.x) >> 5;
    if (n >= MAX_NODES) return;

    const int cnt = min(g_count[n], MAXDEG);
    // lane l holds edge ids for slots l and 32+l
    int e0 = 0, e1 = 0;
    if (lane < cnt) e0 = g_slots[n * MAXDEG + lane];
    if (32 + lane < cnt) e1 = g_slots[n * MAXDEG + 32 + lane];

    float4 a0 = make_float4(0.f, 0.f, 0.f, 0.f);
    float4 a1 = a0;
    float4 a2 = a0;
    for (int j = 0; j < cnt; ++j) {
        const int e = __shfl_sync(0xFFFFFFFFu, (j < 32) ? e0 : e1, j & 31);
        const float4* r = reinterpret_cast<const float4*>(x2) + (size_t)e * ROW4;
        const float4 v0 = __ldg(r + lane);
        const float4 v1 = __ldg(r + 32 + lane);
        a0.x += v0.x; a0.y += v0.y; a0.z += v0.z; a0.w += v0.w;
        a1.x += v1.x; a1.y += v1.y; a1.z += v1.z; a1.w += v1.w;
        if (lane < 8) {
            const float4 v2 = __ldg(r + 64 + lane);
            a2.x += v2.x; a2.y += v2.y; a2.z += v2.z; a2.w += v2.w;
        }
    }
    float4* w = reinterpret_cast<float4*>(g_scatter) + (size_t)n * ROW4;
    w[lane] = a0;
    w[32 + lane] = a1;
    if (lane < 8) w[64 + lane] = a2;
}

// ---------------------------------------------------------------------------
// K3: overflow cleanup (normally zero work) — vector RED into node rows
// ---------------------------------------------------------------------------
__global__ void overflow_kernel(const float* __restrict__ x2,
                                const int* __restrict__ idxs) {
    const int cnt = min(g_ovf_cnt, OVF_CAP);
    const int total = cnt * ROW4;
    for (int t = blockIdx.x * blockDim.x + threadIdx.x; t < total;
         t += gridDim.x * blockDim.x) {
        const int entry = t / ROW4;
        const int c = t - entry * ROW4;
        const int e = g_ovf[entry];
        const int node = idxs[e];
        const float4 v = reinterpret_cast<const float4*>(x2)[(size_t)e * ROW4 + c];
        float* dst = g_scatter + (size_t)node * ROW + c * 4;
        asm volatile(
            "red.relaxed.gpu.global.add.v4.f32 [%0], {%1, %2, %3, %4};"
            :: "l"(__cvta_generic_to_global(dst)),
               "f"(v.x), "f"(v.y), "f"(v.z), "f"(v.w)
            : "memory");
    }
}

// ---------------------------------------------------------------------------
// Contraction codegen (constant-memory 3j values, smem path weights)
// ---------------------------------------------------------------------------
template <int P, int S, int SEND>
__device__ __forceinline__ void path_entries(float* pacc, const float* a,
                                             const float* b) {
    if constexpr (S < SEND) {
        constexpr int i = TAB.e[S].i;
        constexpr int j = TAB.e[S].j;
        constexpr int kk = TAB.e[S].k - PATH_K_BASE[P];
        pacc[kk] = fmaf(a[i] * b[j], c_VAL[S], pacc[kk]);
        path_entries<P, S + 1, SEND>(pacc, a, b);
    }
}

template <int P>
__device__ __forceinline__ void do_path(float* acc, const float* a,
                                        const float* b,
                                        const float* __restrict__ wsm,
                                        int lane) {
    constexpr int kc = PATH_K_CNT[P];
    float pacc[5] = {0.f, 0.f, 0.f, 0.f, 0.f};
    path_entries<P, PSTART.v[P], PSTART.v[P + 1]>(pacc, a, b);
    const float w = wsm[P * 32 + lane];
#pragma unroll
    for (int kk = 0; kk < kc; ++kk)
        acc[kk] = fmaf(w, pacc[kk], acc[kk]);
}

// ---------------------------------------------------------------------------
// K4: per-edge contraction. warp = edge, lane = u (mul channel). (R5 form)
// ---------------------------------------------------------------------------
#define CWARPS 8

__global__ __launch_bounds__(CWARPS * 32, 5)
void compute_kernel(const float* __restrict__ x1, const int* __restrict__ idxs,
                    const float* __restrict__ weights, float* __restrict__ out,
                    int E, int totalWarps) {
    __shared__ float bufA[CWARPS][ROW];
    __shared__ float bufB[CWARPS][ROW];
    __shared__ float wsm[NPATHS * 32]; // [p][u]
    const int lane = threadIdx.x & 31;
    const int wip  = threadIdx.x >> 5;
    const int gw   = blockIdx.x * CWARPS + wip;
    float* bA = bufA[wip];
    float* bB = bufB[wip];
    float4* bA4 = reinterpret_cast<float4*>(bA);
    float4* bB4 = reinterpret_cast<float4*>(bB);

    for (int t = threadIdx.x; t < NPATHS * 32; t += CWARPS * 32) {
        const int p = t >> 5;
        const int u = t & 31;
        wsm[t] = weights[u * NPATHS + p];
    }
    __syncthreads();

    for (int e = gw; e < E; e += totalWarps) {
        const int node = __ldg(idxs + e);

        const float4* p1 = reinterpret_cast<const float4*>(x1 + (size_t)e * ROW);
        const float4* p2 = reinterpret_cast<const float4*>(g_scatter + (size_t)node * ROW);
        float4 A0 = __ldg(p1 + lane);
        float4 A1 = __ldg(p1 + 32 + lane);
        float4 A2 = {};
        float4 B0 = __ldg(p2 + lane);
        float4 B1 = __ldg(p2 + 32 + lane);
        float4 B2 = {};
        if (lane < 8) {
            A2 = __ldg(p1 + 64 + lane);
            B2 = __ldg(p2 + 64 + lane);
        }
        bA4[lane] = A0; bA4[32 + lane] = A1;
        bB4[lane] = B0; bB4[32 + lane] = B1;
        if (lane < 8) { bA4[64 + lane] = A2; bB4[64 + lane] = B2; }
        __syncwarp();

        // transposed lane-private reads (stride-9 is conflict-free)
        float a[9], b[9];
#pragma unroll
        for (int i = 0; i < 9; ++i) a[i] = bA[lane * 9 + i];
#pragma unroll
        for (int j = 0; j < 9; ++j) b[j] = bB[lane * 9 + j];

        // acc writes land in the SAME lane-private 9-float region -> no sync
        {
            float acc[1] = {0.f};
            do_path<0>(acc, a, b, wsm, lane);
            do_path<1>(acc, a, b, wsm, lane);
            do_path<2>(acc, a, b, wsm, lane);
            bA[lane * 9 + 0] = acc[0];
        }
        {
            float acc[3] = {0.f, 0.f, 0.f};
            do_path<3>(acc, a, b, wsm, lane);
            do_path<4>(acc, a, b, wsm, lane);
            do_path<5>(acc, a, b, wsm, lane);
            do_path<6>(acc, a, b, wsm, lane);
#pragma unroll
            for (int kk = 0; kk < 3; ++kk) bA[lane * 9 + 1 + kk] = acc[kk];
        }
        {
            float acc[5] = {0.f, 0.f, 0.f, 0.f, 0.f};
            do_path<7>(acc, a, b, wsm, lane);
            do_path<8>(acc, a, b, wsm, lane);
            do_path<9>(acc, a, b, wsm, lane);
            do_path<10>(acc, a, b, wsm, lane);
#pragma unroll
            for (int kk = 0; kk < 5; ++kk) bA[lane * 9 + 4 + kk] = acc[kk];
        }
        __syncwarp();

        float4* ov = reinterpret_cast<float4*>(out + (size_t)e * ROW);
        ov[lane] = bA4[lane];
        ov[32 + lane] = bA4[32 + lane];
        if (lane < 8) ov[64 + lane] = bA4[64 + lane];
        __syncwarp();
    }
}

// ---------------------------------------------------------------------------
// launch
// ---------------------------------------------------------------------------
extern "C" void kernel_launch(void* const* d_in, const int* in_sizes, int n_in,
                              void* d_out, int out_size) {
    const float* x1   = (const float*)d_in[0];
    const float* x2   = (const float*)d_in[1];
    const int*   idxs = (const int*)d_in[2];

    const float* w3j = nullptr;
    const float* weights = nullptr;
    for (int i = 3; i < n_in; ++i) {
        if (in_sizes[i] == NPATHS * 729) w3j = (const float*)d_in[i];
        else if (in_sizes[i] == MUL * NPATHS) weights = (const float*)d_in[i];
    }

    const int E = in_sizes[0] / ROW;
    float* out = (float*)d_out;

    zero_counters_kernel<<<(MAX_NODES + 255) / 256, 256>>>();
    fill_kernel<<<(E + 255) / 256, 256>>>(idxs, E, w3j);
    accumulate_kernel<<<(MAX_NODES * 32 + 255) / 256, 256>>>(x2);
    overflow_kernel<<<16, 256>>>(x2, idxs);

    void* cval_dev = nullptr;
    cudaGetSymbolAddress(&cval_dev, g_cval);
    cudaMemcpyToSymbolAsync(c_VAL, cval_dev, 96 * sizeof(float), 0,
                            cudaMemcpyDeviceToDevice, 0);

    const int blocks = 740; // 148 SMs * 5 blocks
    const int totalWarps = blocks * CWARPS;
    compute_kernel<<<blocks, CWARPS * 32>>>(x1, idxs, weights, out, E, totalWarps);
}

// round 8
// speedup vs baseline: 1.1217x; 1.1217x over previous
#include <cuda_runtime.h>
#include <utility>
#include <cstdint>

// ---------------------------------------------------------------------------
// Problem constants (fixed: LS=[0,1,2], OFF=[0,1,4], 11 paths, MUL=32, dim=9)
// ---------------------------------------------------------------------------
#define BASE_DIM 9
#define MUL 32
#define NPATHS 11
#define MAX_NODES 10000
#define ROW (MUL * BASE_DIM) /* 288 */
#define ROWB (ROW * 4)       /* 1152 bytes */

struct BEntry { int i, j, k, p; };
struct BTable { BEntry e[96]; int n; };

constexpr BTable build_table() {
    constexpr int ls[3]  = {0, 1, 2};
    constexpr int off[3] = {0, 1, 4};
    constexpr int paths[NPATHS][3] = {
        {0,0,0},{1,1,0},{2,2,0},
        {0,1,1},{1,0,1},{1,2,1},{2,1,1},
        {0,2,2},{1,1,2},{2,0,2},{2,2,2}};
    BTable t{};
    t.n = 0;
    for (int p = 0; p < NPATHS; ++p) {
        const int la = ls[paths[p][0]], lb = ls[paths[p][1]], lc = ls[paths[p][2]];
        for (int m1 = -la; m1 <= la; ++m1)
        for (int m2 = -lb; m2 <= lb; ++m2)
        for (int m3 = -lc; m3 <= lc; ++m3) {
            const int a = m1 < 0 ? -m1 : m1;
            const int b = m2 < 0 ? -m2 : m2;
            const int c = m3 < 0 ? -m3 : m3;
            const int d = a > b ? a - b : b - a;
            if (c != a + b && c != d) continue;
            const int negs = (m1 < 0) + (m2 < 0) + (m3 < 0);
            if (negs & 1) continue;
            t.e[t.n].i = off[paths[p][0]] + la + m1;
            t.e[t.n].j = off[paths[p][1]] + lb + m2;
            t.e[t.n].k = off[paths[p][2]] + lc + m3;
            t.e[t.n].p = p;
            ++t.n;
        }
    }
    return t;
}

constexpr BTable TAB = build_table();
constexpr int NS = TAB.n;
static_assert(NS == 83, "expected 83 structural nonzeros");

struct PStarts { int v[NPATHS + 1]; };
constexpr PStarts build_pstarts() {
    PStarts r{};
    for (int p = 0; p <= NPATHS; ++p) {
        int c = 0;
        for (int s = 0; s < NS; ++s) if (TAB.e[s].p < p) ++c;
        r.v[p] = c;
    }
    return r;
}
constexpr PStarts PSTART = build_pstarts();

constexpr int PATH_K_BASE[NPATHS] = {0,0,0, 1,1,1,1, 4,4,4,4};
constexpr int PATH_K_CNT [NPATHS] = {1,1,1, 3,3,3,3, 5,5,5,5};

__constant__ BTable c_TAB = TAB;
__constant__ float c_VAL[96];

// ---------------------------------------------------------------------------
// Device scratch
// ---------------------------------------------------------------------------
__device__ __align__(16) float g_scatter[(size_t)MAX_NODES * ROW]; // 11.52 MB
__device__ float g_cval[96];

// ---------------------------------------------------------------------------
// K1: zero the scatter buffer; block 0 also extracts w3j entry values
// ---------------------------------------------------------------------------
__global__ void zero_tables_kernel(const float* __restrict__ w3j) {
    if (blockIdx.x == 0 && threadIdx.x < 96) {
        const int s = threadIdx.x;
        if (s < NS) {
            const BEntry en = c_TAB.e[s];
            g_cval[s] = w3j[en.p * 729 + en.i * 81 + en.j * 9 + en.k];
        } else {
            g_cval[s] = 0.f;
        }
    }
    const int total = MAX_NODES * (ROW / 4);
    float4* p = reinterpret_cast<float4*>(g_scatter);
    for (int i = blockIdx.x * blockDim.x + threadIdx.x; i < total;
         i += gridDim.x * blockDim.x) {
        p[i] = make_float4(0.f, 0.f, 0.f, 0.f);
    }
}

// ---------------------------------------------------------------------------
// K2: scatter-add x2 rows into node rows via 128-bit vector reductions
// ---------------------------------------------------------------------------
__global__ void scatter_kernel(const float* __restrict__ x2,
                               const int* __restrict__ idxs, int E) {
    const int t = blockIdx.x * blockDim.x + threadIdx.x;
    const int total = E * (ROW / 4);
    if (t >= total) return;
    const int e = t / (ROW / 4);
    const int c = t - e * (ROW / 4);
    const int node = idxs[e];
    const float4 v = reinterpret_cast<const float4*>(x2)[t];
    float* dst = g_scatter + (size_t)node * ROW + c * 4;
    asm volatile(
        "red.relaxed.gpu.global.add.v4.f32 [%0], {%1, %2, %3, %4};"
        :: "l"(__cvta_generic_to_global(dst)),
           "f"(v.x), "f"(v.y), "f"(v.z), "f"(v.w)
        : "memory");
}

// ---------------------------------------------------------------------------
// Contraction codegen (constant-memory 3j values, smem path weights)
// ---------------------------------------------------------------------------
template <int P, int S, int SEND>
__device__ __forceinline__ void path_entries(float* pacc, const float* a,
                                             const float* b) {
    if constexpr (S < SEND) {
        constexpr int i = TAB.e[S].i;
        constexpr int j = TAB.e[S].j;
        constexpr int kk = TAB.e[S].k - PATH_K_BASE[P];
        pacc[kk] = fmaf(a[i] * b[j], c_VAL[S], pacc[kk]);
        path_entries<P, S + 1, SEND>(pacc, a, b);
    }
}

template <int P>
__device__ __forceinline__ void do_path(float* acc, const float* a,
                                        const float* b,
                                        const float* __restrict__ wsm,
                                        int lane) {
    constexpr int kc = PATH_K_CNT[P];
    float pacc[5] = {0.f, 0.f, 0.f, 0.f, 0.f};
    path_entries<P, PSTART.v[P], PSTART.v[P + 1]>(pacc, a, b);
    const float w = wsm[P * 32 + lane];
#pragma unroll
    for (int kk = 0; kk < kc; ++kk)
        acc[kk] = fmaf(w, pacc[kk], acc[kk]);
}

// ---------------------------------------------------------------------------
// TMA 1D bulk helpers
// ---------------------------------------------------------------------------
__device__ __forceinline__ uint32_t s2u(const void* p) {
    return (uint32_t)__cvta_generic_to_shared(p);
}

__device__ __forceinline__ void bulk_ld(uint32_t dst_smem, const void* src,
                                        uint32_t bytes, uint32_t mbar) {
    asm volatile(
        "cp.async.bulk.shared::cta.global.mbarrier::complete_tx::bytes "
        "[%0], [%1], %2, [%3];"
        :: "r"(dst_smem), "l"(src), "r"(bytes), "r"(mbar) : "memory");
}

__device__ __forceinline__ void bulk_st(void* dst, uint32_t src_smem,
                                        uint32_t bytes) {
    asm volatile(
        "cp.async.bulk.global.shared::cta.bulk_group [%0], [%1], %2;"
        :: "l"(dst), "r"(src_smem), "r"(bytes) : "memory");
}

__device__ __forceinline__ void mbar_init(uint32_t mbar, uint32_t cnt) {
    asm volatile("mbarrier.init.shared::cta.b64 [%0], %1;"
                 :: "r"(mbar), "r"(cnt) : "memory");
}

__device__ __forceinline__ void mbar_expect_tx(uint32_t mbar, uint32_t bytes) {
    asm volatile("mbarrier.arrive.expect_tx.shared::cta.b64 _, [%0], %1;"
                 :: "r"(mbar), "r"(bytes) : "memory");
}

__device__ __forceinline__ void mbar_wait(uint32_t mbar, uint32_t phase) {
    uint32_t done;
    do {
        asm volatile(
            "{\n\t.reg .pred p;\n\t"
            "mbarrier.try_wait.parity.acquire.cta.shared::cta.b64 p, [%1], %2, 0x989680;\n\t"
            "selp.b32 %0, 1, 0, p;\n\t}"
            : "=r"(done) : "r"(mbar), "r"(phase) : "memory");
    } while (!done);
}

// ---------------------------------------------------------------------------
// K3: per-edge contraction, TMA bulk in/out. warp = edge, lane = u.
// ---------------------------------------------------------------------------
#define CWARPS 8

struct __align__(16) WarpBuf {
    float x1b[ROW];
    float bb[ROW];
    float ob[2][ROW];
};

__global__ __launch_bounds__(CWARPS * 32, 5)
void compute_kernel(const float* __restrict__ x1, const int* __restrict__ idxs,
                    const float* __restrict__ weights, float* __restrict__ out,
                    int E, int totalWarps) {
    __shared__ WarpBuf wb[CWARPS];
    __shared__ __align__(8) unsigned long long mbars[CWARPS];
    __shared__ float wsm[NPATHS * 32]; // [p][u]

    const int lane = threadIdx.x & 31;
    const int wip  = threadIdx.x >> 5;
    const int gw   = blockIdx.x * CWARPS + wip;

    float* x1b = wb[wip].x1b;
    float* bb  = wb[wip].bb;
    const uint32_t x1s = s2u(x1b);
    const uint32_t bs  = s2u(bb);
    const uint32_t os[2] = { s2u(wb[wip].ob[0]), s2u(wb[wip].ob[1]) };
    const uint32_t mb  = s2u(&mbars[wip]);

    for (int t = threadIdx.x; t < NPATHS * 32; t += CWARPS * 32) {
        const int p = t >> 5;
        const int u = t & 31;
        wsm[t] = weights[u * NPATHS + p];
    }
    if (lane == 0) mbar_init(mb, 1);
    __syncthreads();

    uint32_t phase = 0;
    int sel = 0;
    int iter = 0;

    for (int e = gw; e < E; e += totalWarps, ++iter) {
        __syncwarp(); // all lanes done reading x1b/bb from previous iter
        if (lane == 0) {
            const int node = __ldg(idxs + e);
            mbar_expect_tx(mb, 2 * ROWB);
            bulk_ld(x1s, x1 + (size_t)e * ROW, ROWB, mb);
            bulk_ld(bs, g_scatter + (size_t)node * ROW, ROWB, mb);
        }
        mbar_wait(mb, phase);
        phase ^= 1;

        // transposed lane-private reads (stride-9, conflict-free)
        float a[9], b[9];
#pragma unroll
        for (int i = 0; i < 9; ++i) a[i] = x1b[lane * 9 + i];
#pragma unroll
        for (int j = 0; j < 9; ++j) b[j] = bb[lane * 9 + j];

        float acc0[1] = {0.f};
        do_path<0>(acc0, a, b, wsm, lane);
        do_path<1>(acc0, a, b, wsm, lane);
        do_path<2>(acc0, a, b, wsm, lane);
        float acc1[3] = {0.f, 0.f, 0.f};
        do_path<3>(acc1, a, b, wsm, lane);
        do_path<4>(acc1, a, b, wsm, lane);
        do_path<5>(acc1, a, b, wsm, lane);
        do_path<6>(acc1, a, b, wsm, lane);
        float acc2[5] = {0.f, 0.f, 0.f, 0.f, 0.f};
        do_path<7>(acc2, a, b, wsm, lane);
        do_path<8>(acc2, a, b, wsm, lane);
        do_path<9>(acc2, a, b, wsm, lane);
        do_path<10>(acc2, a, b, wsm, lane);

        // make sure the out-buffer we're about to overwrite has been drained
        if (iter >= 2 && lane == 0)
            asm volatile("cp.async.bulk.wait_group 1;" ::: "memory");
        __syncwarp();

        float* ob = wb[wip].ob[sel];
        ob[lane * 9 + 0] = acc0[0];
#pragma unroll
        for (int kk = 0; kk < 3; ++kk) ob[lane * 9 + 1 + kk] = acc1[kk];
#pragma unroll
        for (int kk = 0; kk < 5; ++kk) ob[lane * 9 + 4 + kk] = acc2[kk];
        __syncwarp();

        if (lane == 0) {
            asm volatile("fence.proxy.async.shared::cta;" ::: "memory");
            bulk_st(out + (size_t)e * ROW, os[sel], ROWB);
            asm volatile("cp.async.bulk.commit_group;" ::: "memory");
        }
        sel ^= 1;
    }
    if (lane == 0)
        asm volatile("cp.async.bulk.wait_group 0;" ::: "memory");
}

// ---------------------------------------------------------------------------
// launch
// ---------------------------------------------------------------------------
extern "C" void kernel_launch(void* const* d_in, const int* in_sizes, int n_in,
                              void* d_out, int out_size) {
    const float* x1   = (const float*)d_in[0];
    const float* x2   = (const float*)d_in[1];
    const int*   idxs = (const int*)d_in[2];

    const float* w3j = nullptr;
    const float* weights = nullptr;
    for (int i = 3; i < n_in; ++i) {
        if (in_sizes[i] == NPATHS * 729) w3j = (const float*)d_in[i];
        else if (in_sizes[i] == MUL * NPATHS) weights = (const float*)d_in[i];
    }

    const int E = in_sizes[0] / ROW;
    float* out = (float*)d_out;

    zero_tables_kernel<<<1024, 256>>>(w3j);
    scatter_kernel<<<(E * (ROW / 4) + 255) / 256, 256>>>(x2, idxs, E);

    void* cval_dev = nullptr;
    cudaGetSymbolAddress(&cval_dev, g_cval);
    cudaMemcpyToSymbolAsync(c_VAL, cval_dev, 96 * sizeof(float), 0,
                            cudaMemcpyDeviceToDevice, 0);

    const int blocks = 740; // 148 SMs * 5 blocks
    const int totalWarps = blocks * CWARPS;
    compute_kernel<<<blocks, CWARPS * 32>>>(x1, idxs, weights, out, E, totalWarps);
}